// round 5
// baseline (speedup 1.0000x reference)
#include <cuda_runtime.h>
#include <cuda_bf16.h>
#include <cstdint>
#include <math.h>

#define K_DIM 128
#define D_DIM 256
#define TILE_M 128
#define NTHREADS 256
#define DC 64
#define SB 144               // smem row stride bytes (72 bf16): conflict-free ldmatrix
#define ATILE 18432          // 128 * 144
#define BTILE 36864          // Bh + Bl contiguous
#define STAGE 55296          // ATILE + BTILE per stage

// ---- dynamic smem layout (bytes) ----
#define SMEM_AH(s)  ((s) * STAGE)
#define SMEM_BH(s)  ((s) * STAGE + ATILE)
#define SMEM_MISC   110592
#define SMEM_C2     (SMEM_MISC + 0)      // 128 f32
#define SMEM_X2     (SMEM_MISC + 512)    // 128 f32
#define SMEM_BV     (SMEM_MISC + 1024)   // 2*128 f32
#define SMEM_BS     (SMEM_MISC + 2048)   // 2*128 f32
#define SMEM_BI     (SMEM_MISC + 3072)   // 2*128 i32
#define SMEM_IDX    (SMEM_MISC + 4096)   // 128 i32
#define SMEM_FCNT   (SMEM_MISC + 4608)
#define SMEM_FLIST  (SMEM_MISC + 4612)   // 128 i32
#define SMEM_TOTAL  (SMEM_MISC + 5200)

__device__ float g_c2[K_DIM];
// Pre-split B: per chunk [Bh tile 18432 B][Bl tile 18432 B], padded layout == smem image
__device__ __align__(16) unsigned char g_B[4 * BTILE];

// ---------------- PTX helpers ----------------
__device__ __forceinline__ uint32_t smem_u32(const void* p) {
    uint32_t a;
    asm("{ .reg .u64 t; cvta.to.shared.u64 t, %1; cvt.u32.u64 %0, t; }"
        : "=r"(a) : "l"(p));
    return a;
}
__device__ __forceinline__ void ldsm4(uint32_t* r, uint32_t addr) {
    asm volatile("ldmatrix.sync.aligned.m8n8.x4.shared.b16 {%0,%1,%2,%3}, [%4];"
                 : "=r"(r[0]), "=r"(r[1]), "=r"(r[2]), "=r"(r[3]) : "r"(addr));
}
__device__ __forceinline__ void mma_bf16(float* d, const uint32_t* a, const uint32_t* b) {
    asm volatile("mma.sync.aligned.m16n8k16.row.col.f32.bf16.bf16.f32 "
                 "{%0,%1,%2,%3}, {%4,%5,%6,%7}, {%8,%9}, {%0,%1,%2,%3};"
                 : "+f"(d[0]), "+f"(d[1]), "+f"(d[2]), "+f"(d[3])
                 : "r"(a[0]), "r"(a[1]), "r"(a[2]), "r"(a[3]), "r"(b[0]), "r"(b[1]));
}
__device__ __forceinline__ void cp16(uint32_t smaddr, const void* gaddr) {
    asm volatile("cp.async.ca.shared.global [%0], [%1], 16;"
                 :: "r"(smaddr), "l"(gaddr) : "memory");
}
#define CP_COMMIT() asm volatile("cp.async.commit_group;" ::: "memory")
#define CP_WAIT0()  asm volatile("cp.async.wait_group 0;" ::: "memory")

__device__ __forceinline__ uint32_t pack_bf2(float a, float b) {
    __nv_bfloat16 ha = __float2bfloat16_rn(a), hb = __float2bfloat16_rn(b);
    uint16_t ra = *reinterpret_cast<uint16_t*>(&ha);
    uint16_t rb = *reinterpret_cast<uint16_t*>(&hb);
    return (uint32_t)ra | ((uint32_t)rb << 16);
}

// ---------------- prep: ||c_k||^2 + pre-split B hi/lo in padded layout ----------------
__global__ void prep_kernel(const float* __restrict__ C) {
    int tid = threadIdx.x;
    if (tid < K_DIM) {
        float s = 0.f;
        const float* row = C + (size_t)tid * D_DIM;
#pragma unroll 8
        for (int d = 0; d < D_DIM; ++d) s = fmaf(row[d], row[d], s);
        g_c2[tid] = s;
    }
    for (int i = tid; i < 4 * 128 * 64; i += NTHREADS) {
        int ch = i >> 13, r = (i >> 6) & 127, d = i & 63;
        float v = C[(size_t)r * D_DIM + ch * DC + d];
        __nv_bfloat16 h = __float2bfloat16_rn(v);
        __nv_bfloat16 l = __float2bfloat16_rn(v - __bfloat162float(h));
        *reinterpret_cast<uint16_t*>(&g_B[ch * BTILE + r * SB + d * 2]) =
            *reinterpret_cast<uint16_t*>(&h);
        *reinterpret_cast<uint16_t*>(&g_B[ch * BTILE + ATILE + r * SB + d * 2]) =
            *reinterpret_cast<uint16_t*>(&l);
    }
}

// ---------------- main ----------------
__global__ __launch_bounds__(NTHREADS, 2)
void assign_kernel(const float* __restrict__ seq, const float* __restrict__ u,
                   const float* __restrict__ C, float* __restrict__ assign,
                   int N) {
    extern __shared__ char smem[];
    const uint32_t sm = smem_u32(smem);
    const int tid = threadIdx.x;
    const int wid = tid >> 5;
    const int lane = tid & 31;
    const int row0 = blockIdx.x * TILE_M;

    float* c2s = (float*)(smem + SMEM_C2);
    float* x2s = (float*)(smem + SMEM_X2);
    float* bvs = (float*)(smem + SMEM_BV);
    float* bss = (float*)(smem + SMEM_BS);
    int*   bis = (int*)(smem + SMEM_BI);
    int*   idxs = (int*)(smem + SMEM_IDX);
    int*   fcnt = (int*)(smem + SMEM_FCNT);
    int*   flist = (int*)(smem + SMEM_FLIST);

    if (tid < K_DIM) c2s[tid] = g_c2[tid];
    if (tid == 0) *fcnt = 0;

    const int wr = wid >> 1;
    const int wc = wid & 1;

    float acc[2][8][4];
#pragma unroll
    for (int mi = 0; mi < 2; mi++)
#pragma unroll
        for (int ni = 0; ni < 8; ni++)
#pragma unroll
            for (int j = 0; j < 4; j++) acc[mi][ni][j] = 0.f;

    float4 av[8];

    // ---- helpers inlined via macros ----
#define LD_A(CH) do {                                                            \
    _Pragma("unroll")                                                            \
    for (int i = 0; i < 8; ++i) {                                                \
        int f = tid + NTHREADS * i;                                              \
        int row = f >> 4, c4 = f & 15, grow = row0 + row;                        \
        av[i] = make_float4(0.f, 0.f, 0.f, 0.f);                                 \
        if (grow < N)                                                            \
            av[i] = *reinterpret_cast<const float4*>(                            \
                seq + (size_t)grow * D_DIM + (CH) * DC + 4 * c4);                \
    }                                                                            \
} while (0)

#define CP_B(CH, S) do {                                                         \
    const unsigned char* src = g_B + (CH) * BTILE;                               \
    uint32_t dst = sm + SMEM_BH(S);                                              \
    _Pragma("unroll")                                                            \
    for (int j = 0; j < 9; ++j) {                                                \
        int off = (tid + NTHREADS * j) * 16;                                     \
        cp16(dst + off, src + off);                                              \
    }                                                                            \
} while (0)

#define CVT_A(S, FIRST) do {                                                     \
    char* dst = smem + SMEM_AH(S);                                               \
    _Pragma("unroll")                                                            \
    for (int i = 0; i < 8; ++i) {                                                \
        int f = tid + NTHREADS * i;                                              \
        int row = f >> 4, c4 = f & 15;                                           \
        float4 v = av[i];                                                        \
        float part = v.x * v.x + v.y * v.y + v.z * v.z + v.w * v.w;              \
        _Pragma("unroll")                                                        \
        for (int o = 8; o >= 1; o >>= 1)                                         \
            part += __shfl_xor_sync(0xffffffffu, part, o);                       \
        if ((lane & 15) == 0) {                                                  \
            if (FIRST) x2s[row] = part; else x2s[row] += part;                   \
        }                                                                        \
        *reinterpret_cast<uint2*>(dst + (uint32_t)row * SB + c4 * 8) =           \
            make_uint2(pack_bf2(v.x, v.y), pack_bf2(v.z, v.w));                  \
    }                                                                            \
} while (0)

    // ---- prologue: stage 0 ----
    CP_B(0, 0);
    CP_COMMIT();
    LD_A(0);
    CVT_A(0, true);
    CP_WAIT0();
    __syncthreads();

    // ---- pipelined mainloop ----
#pragma unroll
    for (int ch = 0; ch < 4; ++ch) {
        const int cur = ch & 1, nxt = cur ^ 1;
        if (ch < 3) {
            CP_B(ch + 1, nxt);
            CP_COMMIT();
            LD_A(ch + 1);
        }
        // MMA on stage cur
        const uint32_t ahBase = sm + SMEM_AH(cur);
        const uint32_t bhBase = sm + SMEM_BH(cur);
#pragma unroll
        for (int ks = 0; ks < 4; ++ks) {
            uint32_t ah[2][4];
            const uint32_t a_lane_off =
                (uint32_t)(lane & 15) * SB + (uint32_t)(lane >> 4) * 16 + (uint32_t)ks * 32;
#pragma unroll
            for (int mi = 0; mi < 2; ++mi)
                ldsm4(ah[mi], ahBase + (uint32_t)(wr * 32 + mi * 16) * SB + a_lane_off);
            const uint32_t b_lane_off =
                (uint32_t)((lane & 7) + ((lane >> 4) << 3)) * SB +
                (uint32_t)ks * 32 + (uint32_t)(((lane >> 3) & 1) << 4);
#pragma unroll
            for (int np = 0; np < 4; ++np) {
                uint32_t boff = (uint32_t)(wc * 64 + np * 16) * SB + b_lane_off;
                uint32_t bh[4], bl[4];
                ldsm4(bh, bhBase + boff);
                ldsm4(bl, bhBase + ATILE + boff);
#pragma unroll
                for (int mi = 0; mi < 2; ++mi) {
#pragma unroll
                    for (int t = 0; t < 2; ++t) {
                        float* d = acc[mi][np * 2 + t];
                        mma_bf16(d, ah[mi], bh + 2 * t);   // xh*ch
                        mma_bf16(d, ah[mi], bl + 2 * t);   // xh*cl
                    }
                }
            }
        }
        if (ch < 3) {
            CVT_A(nxt, false);
            CP_WAIT0();
        }
        __syncthreads();
    }

    // ---- epilogue: logits, per-row top-2, argmax ----
    const int g = lane >> 2;
    const int tig = lane & 3;
#pragma unroll
    for (int mi = 0; mi < 2; ++mi) {
#pragma unroll
        for (int half = 0; half < 2; ++half) {
            int row = wr * 32 + mi * 16 + g + 8 * half;
            int grow = row0 + row;
            float x2r = x2s[row];
            const float* urow = u + (size_t)(grow < N ? grow : 0) * K_DIM + wc * 64;
            float best = -INFINITY, second = -INFINITY;
            int bidx = 0;
#pragma unroll
            for (int ni = 0; ni < 8; ++ni) {
                int col = ni * 8 + tig * 2;
                float2 uu = *reinterpret_cast<const float2*>(urow + col);
#pragma unroll
                for (int j = 0; j < 2; ++j) {
                    int k = wc * 64 + col + j;
                    float dot = acc[mi][ni][2 * half + j];
                    float sq = fmaxf(x2r - 2.f * dot + c2s[k], 0.f);
                    float uv = j ? uu.y : uu.x;
                    float gb = -logf(-logf(uv + 1e-10f) + 1e-10f);
                    float lg = sqrtf(sq) + gb;
                    if (lg > best) { second = best; best = lg; bidx = k; }
                    else if (lg > second) { second = lg; }
                }
            }
#pragma unroll
            for (int o = 1; o <= 2; o <<= 1) {
                float b2 = __shfl_xor_sync(0xffffffffu, best, o);
                float s2 = __shfl_xor_sync(0xffffffffu, second, o);
                int i2 = __shfl_xor_sync(0xffffffffu, bidx, o);
                float lo = fminf(best, b2);
                if (b2 > best || (b2 == best && i2 < bidx)) {
                    second = fmaxf(lo, s2); best = b2; bidx = i2;
                } else {
                    second = fmaxf(lo, second);
                }
            }
            if (tig == 0) {
                bvs[wc * 128 + row] = best;
                bss[wc * 128 + row] = second;
                bis[wc * 128 + row] = bidx;
            }
        }
    }
    __syncthreads();

    // combine halves; flag near-ties for exact fp32 recompute
    if (tid < 128) {
        float v0 = bvs[tid], v1 = bvs[128 + tid];
        float s0 = bss[tid], s1 = bss[128 + tid];
        bool h1 = (v1 > v0);
        float ball = h1 ? v1 : v0;
        float sall = fmaxf(fminf(v0, v1), h1 ? s1 : s0);
        idxs[tid] = h1 ? bis[128 + tid] : bis[tid];
        if (row0 + tid < N && ball - sall < 3e-3f) {
            int p = atomicAdd(fcnt, 1);
            flist[p] = tid;
        }
    }
    __syncthreads();

    // ---- exact fp32 fallback for flagged rows (rare: ~0.3/CTA) ----
    int nf = *fcnt;
    for (int f = 0; f < nf; ++f) {
        int row = flist[f];
        int grow = row0 + row;
        {
            int k = tid & 127, h = tid >> 7;
            const float* xr = seq + (size_t)grow * D_DIM + h * 128;
            const float* cr = C + (size_t)k * D_DIM + h * 128;
            float p = 0.f;
#pragma unroll 8
            for (int d = 0; d < 128; ++d) p = fmaf(xr[d], cr[d], p);
            bvs[tid] = p;
        }
        __syncthreads();
        if (tid < 128) {
            float dot = bvs[tid] + bvs[tid + 128];
            float sq = fmaxf(x2s[row] - 2.f * dot + c2s[tid], 0.f);
            float uv = u[(size_t)grow * K_DIM + tid];
            bss[tid] = sqrtf(sq) - logf(-logf(uv + 1e-10f) + 1e-10f);
        }
        __syncthreads();
        if (tid == 0) {
            float bv = -INFINITY; int bi = 0;
            for (int k = 0; k < K_DIM; ++k)
                if (bss[k] > bv) { bv = bss[k]; bi = k; }
            idxs[row] = bi;
        }
        __syncthreads();
    }

    // ---- coalesced one-hot store ----
#pragma unroll
    for (int it = 0; it < 16; ++it) {
        int item = tid + NTHREADS * it;
        int row = item >> 5;
        int c4 = item & 31;
        int grow = row0 + row;
        if (grow < N) {
            int hot = idxs[row];
            float4 o = make_float4(0.f, 0.f, 0.f, 0.f);
            if ((hot >> 2) == c4) reinterpret_cast<float*>(&o)[hot & 3] = 1.0f;
            *reinterpret_cast<float4*>(assign + (size_t)grow * K_DIM + 4 * c4) = o;
        }
    }
}

extern "C" void kernel_launch(void* const* d_in, const int* in_sizes, int n_in,
                              void* d_out, int out_size) {
    const float* seq = (const float*)d_in[0];  // [N,256]
    const float* u   = (const float*)d_in[1];  // [N,128]
    const float* C   = (const float*)d_in[2];  // [128,256]

    const int N = in_sizes[1] / K_DIM;
    float* out = (float*)d_out;
    float* assign = out;

    long long need_both = (long long)N * K_DIM + (long long)K_DIM * D_DIM;
    if ((long long)out_size >= need_both) {
        cudaMemcpyAsync(out, C, (size_t)K_DIM * D_DIM * sizeof(float),
                        cudaMemcpyDeviceToDevice);
        assign = out + K_DIM * D_DIM;
    }

    prep_kernel<<<1, NTHREADS>>>(C);

    cudaFuncSetAttribute(assign_kernel,
                         cudaFuncAttributeMaxDynamicSharedMemorySize, SMEM_TOTAL);
    int grid = (N + TILE_M - 1) / TILE_M;
    assign_kernel<<<grid, NTHREADS, SMEM_TOTAL>>>(seq, u, C, assign, N);
}

// round 6
// speedup vs baseline: 1.6465x; 1.6465x over previous
#include <cuda_runtime.h>
#include <cuda_bf16.h>
#include <cstdint>
#include <math.h>

#define K_DIM 128
#define D_DIM 256
#define TILE_M 128
#define NTHREADS 256
#define DC 64
#define SB 144               // smem row stride bytes (72 bf16): conflict-free ldmatrix
#define ATILE 18432          // 128 * 144
#define BTILE 36864          // Bh + Bl contiguous

// ---- dynamic smem layout (bytes): single stage, 2 CTAs/SM ----
#define SMEM_A      0
#define SMEM_BHI    18432
#define SMEM_MISC   55296
#define SMEM_C2     (SMEM_MISC + 0)      // 128 f32
#define SMEM_X2     (SMEM_MISC + 512)    // 128 f32
#define SMEM_BV     (SMEM_MISC + 1024)   // 2*128 f32
#define SMEM_BS     (SMEM_MISC + 2048)   // 2*128 f32
#define SMEM_BI     (SMEM_MISC + 3072)   // 2*128 i32
#define SMEM_IDX    (SMEM_MISC + 4096)   // 128 i32
#define SMEM_FCNT   (SMEM_MISC + 4608)
#define SMEM_FLIST  (SMEM_MISC + 4612)   // 128 i32
#define SMEM_TOTAL  (SMEM_MISC + 5200)   // 60496 B

__device__ float g_c2[K_DIM];
// Pre-split B: per chunk [Bh tile 18432 B][Bl tile 18432 B], padded layout == smem image
__device__ __align__(16) unsigned char g_B[4 * BTILE];

// ---------------- PTX helpers ----------------
__device__ __forceinline__ uint32_t smem_u32(const void* p) {
    uint32_t a;
    asm("{ .reg .u64 t; cvta.to.shared.u64 t, %1; cvt.u32.u64 %0, t; }"
        : "=r"(a) : "l"(p));
    return a;
}
__device__ __forceinline__ void ldsm4(uint32_t* r, uint32_t addr) {
    asm volatile("ldmatrix.sync.aligned.m8n8.x4.shared.b16 {%0,%1,%2,%3}, [%4];"
                 : "=r"(r[0]), "=r"(r[1]), "=r"(r[2]), "=r"(r[3]) : "r"(addr));
}
__device__ __forceinline__ void mma_bf16(float* d, const uint32_t* a, const uint32_t* b) {
    asm volatile("mma.sync.aligned.m16n8k16.row.col.f32.bf16.bf16.f32 "
                 "{%0,%1,%2,%3}, {%4,%5,%6,%7}, {%8,%9}, {%0,%1,%2,%3};"
                 : "+f"(d[0]), "+f"(d[1]), "+f"(d[2]), "+f"(d[3])
                 : "r"(a[0]), "r"(a[1]), "r"(a[2]), "r"(a[3]), "r"(b[0]), "r"(b[1]));
}
__device__ __forceinline__ void cp16(uint32_t smaddr, const void* gaddr) {
    asm volatile("cp.async.ca.shared.global [%0], [%1], 16;"
                 :: "r"(smaddr), "l"(gaddr) : "memory");
}
#define CP_COMMIT() asm volatile("cp.async.commit_group;" ::: "memory")
#define CP_WAIT0()  asm volatile("cp.async.wait_group 0;" ::: "memory")

__device__ __forceinline__ uint32_t pack_bf2(float a, float b) {
    __nv_bfloat16 ha = __float2bfloat16_rn(a), hb = __float2bfloat16_rn(b);
    uint16_t ra = *reinterpret_cast<uint16_t*>(&ha);
    uint16_t rb = *reinterpret_cast<uint16_t*>(&hb);
    return (uint32_t)ra | ((uint32_t)rb << 16);
}

// ---------------- prep: ||c_k||^2 + pre-split B hi/lo in padded smem image ----------------
__global__ void prep_kernel(const float* __restrict__ C) {
    int tid = threadIdx.x;
    if (tid < K_DIM) {
        float s = 0.f;
        const float* row = C + (size_t)tid * D_DIM;
#pragma unroll 8
        for (int d = 0; d < D_DIM; ++d) s = fmaf(row[d], row[d], s);
        g_c2[tid] = s;
    }
    for (int i = tid; i < 4 * 128 * 64; i += NTHREADS) {
        int ch = i >> 13, r = (i >> 6) & 127, d = i & 63;
        float v = C[(size_t)r * D_DIM + ch * DC + d];
        __nv_bfloat16 h = __float2bfloat16_rn(v);
        __nv_bfloat16 l = __float2bfloat16_rn(v - __bfloat162float(h));
        *reinterpret_cast<uint16_t*>(&g_B[ch * BTILE + r * SB + d * 2]) =
            *reinterpret_cast<uint16_t*>(&h);
        *reinterpret_cast<uint16_t*>(&g_B[ch * BTILE + ATILE + r * SB + d * 2]) =
            *reinterpret_cast<uint16_t*>(&l);
    }
}

// ---------------- main ----------------
__global__ __launch_bounds__(NTHREADS, 2)
void assign_kernel(const float* __restrict__ seq, const float* __restrict__ u,
                   const float* __restrict__ C, float* __restrict__ assign,
                   int N) {
    extern __shared__ char smem[];
    const uint32_t sm = smem_u32(smem);
    const int tid = threadIdx.x;
    const int wid = tid >> 5;
    const int lane = tid & 31;
    const int row0 = blockIdx.x * TILE_M;

    float* c2s = (float*)(smem + SMEM_C2);
    float* x2s = (float*)(smem + SMEM_X2);
    float* bvs = (float*)(smem + SMEM_BV);
    float* bss = (float*)(smem + SMEM_BS);
    int*   bis = (int*)(smem + SMEM_BI);
    int*   idxs = (int*)(smem + SMEM_IDX);
    int*   fcnt = (int*)(smem + SMEM_FCNT);
    int*   flist = (int*)(smem + SMEM_FLIST);

    if (tid < K_DIM) c2s[tid] = g_c2[tid];
    if (tid == 0) *fcnt = 0;

    const int wr = wid >> 1;
    const int wc = wid & 1;

    float acc[2][8][4];
#pragma unroll
    for (int mi = 0; mi < 2; mi++)
#pragma unroll
        for (int ni = 0; ni < 8; ni++)
#pragma unroll
            for (int j = 0; j < 4; j++) acc[mi][ni][j] = 0.f;

    float4 av[8];

#define LD_A(CH) do {                                                            \
    _Pragma("unroll")                                                            \
    for (int i = 0; i < 8; ++i) {                                                \
        int f = tid + NTHREADS * i;                                              \
        int row = f >> 4, c4 = f & 15, grow = row0 + row;                        \
        av[i] = make_float4(0.f, 0.f, 0.f, 0.f);                                 \
        if (grow < N)                                                            \
            av[i] = *reinterpret_cast<const float4*>(                            \
                seq + (size_t)grow * D_DIM + (CH) * DC + 4 * c4);                \
    }                                                                            \
} while (0)

#define CP_B(CH) do {                                                            \
    const unsigned char* src = g_B + (CH) * BTILE;                               \
    uint32_t dst = sm + SMEM_BHI;                                                \
    _Pragma("unroll")                                                            \
    for (int j = 0; j < 9; ++j) {                                                \
        int off = (tid + NTHREADS * j) * 16;                                     \
        cp16(dst + off, src + off);                                              \
    }                                                                            \
} while (0)

#define CVT_A(FIRST) do {                                                        \
    char* dst = smem + SMEM_A;                                                   \
    _Pragma("unroll")                                                            \
    for (int i = 0; i < 8; ++i) {                                                \
        int f = tid + NTHREADS * i;                                              \
        int row = f >> 4, c4 = f & 15;                                           \
        float4 v = av[i];                                                        \
        float part = v.x * v.x + v.y * v.y + v.z * v.z + v.w * v.w;              \
        _Pragma("unroll")                                                        \
        for (int o = 8; o >= 1; o >>= 1)                                         \
            part += __shfl_xor_sync(0xffffffffu, part, o);                       \
        if ((lane & 15) == 0) {                                                  \
            if (FIRST) x2s[row] = part; else x2s[row] += part;                   \
        }                                                                        \
        *reinterpret_cast<uint2*>(dst + (uint32_t)row * SB + c4 * 8) =           \
            make_uint2(pack_bf2(v.x, v.y), pack_bf2(v.z, v.w));                  \
    }                                                                            \
} while (0)

    // ---- prologue: chunk 0 staged ----
    CP_B(0);
    CP_COMMIT();
    LD_A(0);
    CVT_A(true);
    CP_WAIT0();
    __syncthreads();

    // ---- mainloop: LDG(ch+1) hidden under MMA(ch); cp.async B overlapped with CVT ----
#pragma unroll
    for (int ch = 0; ch < 4; ++ch) {
        if (ch < 3) LD_A(ch + 1);      // issue global loads early (latency hides under MMA)

        const uint32_t aBase = sm + SMEM_A;
        const uint32_t bBase = sm + SMEM_BHI;
#pragma unroll
        for (int ks = 0; ks < 4; ++ks) {
            uint32_t ah[2][4];
            const uint32_t a_lane_off =
                (uint32_t)(lane & 15) * SB + (uint32_t)(lane >> 4) * 16 + (uint32_t)ks * 32;
#pragma unroll
            for (int mi = 0; mi < 2; ++mi)
                ldsm4(ah[mi], aBase + (uint32_t)(wr * 32 + mi * 16) * SB + a_lane_off);
            const uint32_t b_lane_off =
                (uint32_t)((lane & 7) + ((lane >> 4) << 3)) * SB +
                (uint32_t)ks * 32 + (uint32_t)(((lane >> 3) & 1) << 4);
#pragma unroll
            for (int np = 0; np < 4; ++np) {
                uint32_t boff = (uint32_t)(wc * 64 + np * 16) * SB + b_lane_off;
                uint32_t bh[4], bl[4];
                ldsm4(bh, bBase + boff);
                ldsm4(bl, bBase + ATILE + boff);
#pragma unroll
                for (int mi = 0; mi < 2; ++mi) {
#pragma unroll
                    for (int t = 0; t < 2; ++t) {
                        float* d = acc[mi][np * 2 + t];
                        mma_bf16(d, ah[mi], bh + 2 * t);   // xh*ch
                        mma_bf16(d, ah[mi], bl + 2 * t);   // xh*cl
                    }
                }
            }
        }
        if (ch < 3) {
            __syncthreads();           // all warps done reading smem tiles
            CP_B(ch + 1);
            CP_COMMIT();
            CVT_A(false);              // overlaps with cp.async in flight
            CP_WAIT0();
            __syncthreads();
        }
    }

    // ---- epilogue: logits, per-row top-2, argmax ----
    const int g = lane >> 2;
    const int tig = lane & 3;
#pragma unroll
    for (int mi = 0; mi < 2; ++mi) {
#pragma unroll
        for (int half = 0; half < 2; ++half) {
            int row = wr * 32 + mi * 16 + g + 8 * half;
            int grow = row0 + row;
            float x2r = x2s[row];
            const float* urow = u + (size_t)(grow < N ? grow : 0) * K_DIM + wc * 64;
            float best = -INFINITY, second = -INFINITY;
            int bidx = 0;
#pragma unroll
            for (int ni = 0; ni < 8; ++ni) {
                int col = ni * 8 + tig * 2;
                float2 uu = *reinterpret_cast<const float2*>(urow + col);
#pragma unroll
                for (int j = 0; j < 2; ++j) {
                    int k = wc * 64 + col + j;
                    float dot = acc[mi][ni][2 * half + j];
                    float sq = fmaxf(x2r - 2.f * dot + c2s[k], 0.f);
                    float uv = j ? uu.y : uu.x;
                    float gb = -logf(-logf(uv + 1e-10f) + 1e-10f);
                    float lg = sqrtf(sq) + gb;
                    if (lg > best) { second = best; best = lg; bidx = k; }
                    else if (lg > second) { second = lg; }
                }
            }
#pragma unroll
            for (int o = 1; o <= 2; o <<= 1) {
                float b2 = __shfl_xor_sync(0xffffffffu, best, o);
                float s2 = __shfl_xor_sync(0xffffffffu, second, o);
                int i2 = __shfl_xor_sync(0xffffffffu, bidx, o);
                float lo = fminf(best, b2);
                if (b2 > best || (b2 == best && i2 < bidx)) {
                    second = fmaxf(lo, s2); best = b2; bidx = i2;
                } else {
                    second = fmaxf(lo, second);
                }
            }
            if (tig == 0) {
                bvs[wc * 128 + row] = best;
                bss[wc * 128 + row] = second;
                bis[wc * 128 + row] = bidx;
            }
        }
    }
    __syncthreads();

    // combine halves; flag near-ties for exact fp32 recompute
    if (tid < 128) {
        float v0 = bvs[tid], v1 = bvs[128 + tid];
        float s0 = bss[tid], s1 = bss[128 + tid];
        bool h1 = (v1 > v0);
        float ball = h1 ? v1 : v0;
        float sall = fmaxf(fminf(v0, v1), h1 ? s1 : s0);
        idxs[tid] = h1 ? bis[128 + tid] : bis[tid];
        if (row0 + tid < N && ball - sall < 3e-3f) {
            int p = atomicAdd(fcnt, 1);
            flist[p] = tid;
        }
    }
    __syncthreads();

    // ---- exact fp32 fallback for flagged rows (~0.3/CTA) ----
    int nf = *fcnt;
    for (int f = 0; f < nf; ++f) {
        int row = flist[f];
        int grow = row0 + row;
        {
            int k = tid & 127, h = tid >> 7;
            const float* xr = seq + (size_t)grow * D_DIM + h * 128;
            const float* cr = C + (size_t)k * D_DIM + h * 128;
            float p = 0.f;
#pragma unroll 8
            for (int d = 0; d < 128; ++d) p = fmaf(xr[d], cr[d], p);
            bvs[tid] = p;
        }
        __syncthreads();
        if (tid < 128) {
            float dot = bvs[tid] + bvs[tid + 128];
            float sq = fmaxf(x2s[row] - 2.f * dot + c2s[tid], 0.f);
            float uv = u[(size_t)grow * K_DIM + tid];
            bss[tid] = sqrtf(sq) - logf(-logf(uv + 1e-10f) + 1e-10f);
        }
        __syncthreads();
        if (tid == 0) {
            float bv = -INFINITY; int bi = 0;
            for (int k = 0; k < K_DIM; ++k)
                if (bss[k] > bv) { bv = bss[k]; bi = k; }
            idxs[row] = bi;
        }
        __syncthreads();
    }

    // ---- coalesced one-hot store ----
#pragma unroll
    for (int it = 0; it < 16; ++it) {
        int item = tid + NTHREADS * it;
        int row = item >> 5;
        int c4 = item & 31;
        int grow = row0 + row;
        if (grow < N) {
            int hot = idxs[row];
            float4 o = make_float4(0.f, 0.f, 0.f, 0.f);
            if ((hot >> 2) == c4) reinterpret_cast<float*>(&o)[hot & 3] = 1.0f;
            *reinterpret_cast<float4*>(assign + (size_t)grow * K_DIM + 4 * c4) = o;
        }
    }
}

extern "C" void kernel_launch(void* const* d_in, const int* in_sizes, int n_in,
                              void* d_out, int out_size) {
    const float* seq = (const float*)d_in[0];  // [N,256]
    const float* u   = (const float*)d_in[1];  // [N,128]
    const float* C   = (const float*)d_in[2];  // [128,256]

    const int N = in_sizes[1] / K_DIM;
    float* out = (float*)d_out;
    float* assign = out;

    long long need_both = (long long)N * K_DIM + (long long)K_DIM * D_DIM;
    if ((long long)out_size >= need_both) {
        cudaMemcpyAsync(out, C, (size_t)K_DIM * D_DIM * sizeof(float),
                        cudaMemcpyDeviceToDevice);
        assign = out + K_DIM * D_DIM;
    }

    prep_kernel<<<1, NTHREADS>>>(C);

    cudaFuncSetAttribute(assign_kernel,
                         cudaFuncAttributeMaxDynamicSharedMemorySize, SMEM_TOTAL);
    int grid = (N + TILE_M - 1) / TILE_M;
    assign_kernel<<<grid, NTHREADS, SMEM_TOTAL>>>(seq, u, C, assign, N);
}

// round 7
// speedup vs baseline: 1.6621x; 1.0095x over previous
#include <cuda_runtime.h>
#include <cuda_bf16.h>
#include <cstdint>
#include <math.h>

#define K_DIM 128
#define D_DIM 256
#define TILE_M 128
#define NTHREADS 256
#define DC 64
#define SB 144               // smem row stride bytes (72 bf16): conflict-free ldmatrix
#define ATILE 18432          // 128 * 144
#define STAGE 36864          // A tile + B tile per stage

// ---- dynamic smem layout (bytes): two stages, 2 CTAs/SM ----
#define SMEM_A(s)   ((s) * STAGE)
#define SMEM_B(s)   ((s) * STAGE + ATILE)
#define SMEM_MISC   73728
#define SMEM_C2     (SMEM_MISC + 0)      // 128 f32
#define SMEM_X2     (SMEM_MISC + 512)    // 128 f32
#define SMEM_BV     (SMEM_MISC + 1024)   // 2*128 f32
#define SMEM_BS     (SMEM_MISC + 2048)   // 2*128 f32
#define SMEM_BI     (SMEM_MISC + 3072)   // 2*128 i32
#define SMEM_IDX    (SMEM_MISC + 4096)   // 128 i32
#define SMEM_FCNT   (SMEM_MISC + 4608)
#define SMEM_FLIST  (SMEM_MISC + 4612)   // 128 i32
#define SMEM_TOTAL  (SMEM_MISC + 5200)   // 78928 B

__device__ float g_c2[K_DIM];
// Pre-converted B (bf16 hi only), per chunk, padded layout == smem image
__device__ __align__(16) unsigned char g_B[4 * ATILE];

// ---------------- PTX helpers ----------------
__device__ __forceinline__ uint32_t smem_u32(const void* p) {
    uint32_t a;
    asm("{ .reg .u64 t; cvta.to.shared.u64 t, %1; cvt.u32.u64 %0, t; }"
        : "=r"(a) : "l"(p));
    return a;
}
__device__ __forceinline__ void ldsm4(uint32_t* r, uint32_t addr) {
    asm volatile("ldmatrix.sync.aligned.m8n8.x4.shared.b16 {%0,%1,%2,%3}, [%4];"
                 : "=r"(r[0]), "=r"(r[1]), "=r"(r[2]), "=r"(r[3]) : "r"(addr));
}
__device__ __forceinline__ void mma_bf16(float* d, const uint32_t* a, const uint32_t* b) {
    asm volatile("mma.sync.aligned.m16n8k16.row.col.f32.bf16.bf16.f32 "
                 "{%0,%1,%2,%3}, {%4,%5,%6,%7}, {%8,%9}, {%0,%1,%2,%3};"
                 : "+f"(d[0]), "+f"(d[1]), "+f"(d[2]), "+f"(d[3])
                 : "r"(a[0]), "r"(a[1]), "r"(a[2]), "r"(a[3]), "r"(b[0]), "r"(b[1]));
}
__device__ __forceinline__ void cp16(uint32_t smaddr, const void* gaddr) {
    asm volatile("cp.async.ca.shared.global [%0], [%1], 16;"
                 :: "r"(smaddr), "l"(gaddr) : "memory");
}
#define CP_COMMIT() asm volatile("cp.async.commit_group;" ::: "memory")
#define CP_WAIT0()  asm volatile("cp.async.wait_group 0;" ::: "memory")

__device__ __forceinline__ uint32_t pack_bf2(float a, float b) {
    __nv_bfloat16 ha = __float2bfloat16_rn(a), hb = __float2bfloat16_rn(b);
    uint16_t ra = *reinterpret_cast<uint16_t*>(&ha);
    uint16_t rb = *reinterpret_cast<uint16_t*>(&hb);
    return (uint32_t)ra | ((uint32_t)rb << 16);
}

// ---------------- prep: ||c_k||^2 + pre-convert B bf16 in padded smem image ----------------
__global__ void prep_kernel(const float* __restrict__ C) {
    int tid = threadIdx.x;
    if (tid < K_DIM) {
        float s = 0.f;
        const float* row = C + (size_t)tid * D_DIM;
#pragma unroll 8
        for (int d = 0; d < D_DIM; ++d) s = fmaf(row[d], row[d], s);
        g_c2[tid] = s;
    }
    for (int i = tid; i < 4 * 128 * 64; i += NTHREADS) {
        int ch = i >> 13, r = (i >> 6) & 127, d = i & 63;
        float v = C[(size_t)r * D_DIM + ch * DC + d];
        __nv_bfloat16 h = __float2bfloat16_rn(v);
        *reinterpret_cast<uint16_t*>(&g_B[ch * ATILE + r * SB + d * 2]) =
            *reinterpret_cast<uint16_t*>(&h);
    }
}

// ---------------- main ----------------
__global__ __launch_bounds__(NTHREADS, 2)
void assign_kernel(const float* __restrict__ seq, const float* __restrict__ u,
                   const float* __restrict__ C, float* __restrict__ assign,
                   int N) {
    extern __shared__ char smem[];
    const uint32_t sm = smem_u32(smem);
    const int tid = threadIdx.x;
    const int wid = tid >> 5;
    const int lane = tid & 31;
    const int row0 = blockIdx.x * TILE_M;

    float* c2s = (float*)(smem + SMEM_C2);
    float* x2s = (float*)(smem + SMEM_X2);
    float* bvs = (float*)(smem + SMEM_BV);
    float* bss = (float*)(smem + SMEM_BS);
    int*   bis = (int*)(smem + SMEM_BI);
    int*   idxs = (int*)(smem + SMEM_IDX);
    int*   fcnt = (int*)(smem + SMEM_FCNT);
    int*   flist = (int*)(smem + SMEM_FLIST);

    if (tid < K_DIM) c2s[tid] = g_c2[tid];
    if (tid == 0) *fcnt = 0;

    const int wr = wid >> 1;
    const int wc = wid & 1;

    float acc[2][8][4];
#pragma unroll
    for (int mi = 0; mi < 2; mi++)
#pragma unroll
        for (int ni = 0; ni < 8; ni++)
#pragma unroll
            for (int j = 0; j < 4; j++) acc[mi][ni][j] = 0.f;

    float4 av[8];

#define LD_A(CH) do {                                                            \
    _Pragma("unroll")                                                            \
    for (int i = 0; i < 8; ++i) {                                                \
        int f = tid + NTHREADS * i;                                              \
        int row = f >> 4, c4 = f & 15, grow = row0 + row;                        \
        av[i] = make_float4(0.f, 0.f, 0.f, 0.f);                                 \
        if (grow < N)                                                            \
            av[i] = *reinterpret_cast<const float4*>(                            \
                seq + (size_t)grow * D_DIM + (CH) * DC + 4 * c4);                \
    }                                                                            \
} while (0)

#define CP_B(CH, S) do {                                                         \
    const unsigned char* src = g_B + (CH) * ATILE;                               \
    uint32_t dst = sm + SMEM_B(S);                                               \
    _Pragma("unroll")                                                            \
    for (int j = 0; j < 5; ++j) {                                                \
        int off = (tid + NTHREADS * j) * 16;                                     \
        if (off < ATILE) cp16(dst + off, src + off);                             \
    }                                                                            \
} while (0)

#define CVT_A(S, FIRST) do {                                                     \
    char* dst = smem + SMEM_A(S);                                                \
    _Pragma("unroll")                                                            \
    for (int i = 0; i < 8; ++i) {                                                \
        int f = tid + NTHREADS * i;                                              \
        int row = f >> 4, c4 = f & 15;                                           \
        float4 v = av[i];                                                        \
        float part = v.x * v.x + v.y * v.y + v.z * v.z + v.w * v.w;              \
        _Pragma("unroll")                                                        \
        for (int o = 8; o >= 1; o >>= 1)                                         \
            part += __shfl_xor_sync(0xffffffffu, part, o);                       \
        if ((lane & 15) == 0) {                                                  \
            if (FIRST) x2s[row] = part; else x2s[row] += part;                   \
        }                                                                        \
        *reinterpret_cast<uint2*>(dst + (uint32_t)row * SB + c4 * 8) =           \
            make_uint2(pack_bf2(v.x, v.y), pack_bf2(v.z, v.w));                  \
    }                                                                            \
} while (0)

    // ---- prologue: stage 0 holds chunk 0 ----
    CP_B(0, 0);
    CP_COMMIT();
    LD_A(0);
    CVT_A(0, true);
    CP_WAIT0();
    __syncthreads();

    // ---- pipelined mainloop: ONE sync per chunk ----
#pragma unroll
    for (int ch = 0; ch < 4; ++ch) {
        const int cur = ch & 1, nxt = cur ^ 1;
        if (ch < 3) {
            CP_B(ch + 1, nxt);      // into other stage: no hazard with MMA(cur)
            CP_COMMIT();
            LD_A(ch + 1);           // DRAM latency hides under MMA
        }
        const uint32_t aBase = sm + SMEM_A(cur);
        const uint32_t bBase = sm + SMEM_B(cur);
#pragma unroll
        for (int ks = 0; ks < 4; ++ks) {
            uint32_t ah[2][4];
            const uint32_t a_lane_off =
                (uint32_t)(lane & 15) * SB + (uint32_t)(lane >> 4) * 16 + (uint32_t)ks * 32;
#pragma unroll
            for (int mi = 0; mi < 2; ++mi)
                ldsm4(ah[mi], aBase + (uint32_t)(wr * 32 + mi * 16) * SB + a_lane_off);
            const uint32_t b_lane_off =
                (uint32_t)((lane & 7) + ((lane >> 4) << 3)) * SB +
                (uint32_t)ks * 32 + (uint32_t)(((lane >> 3) & 1) << 4);
#pragma unroll
            for (int np = 0; np < 4; ++np) {
                uint32_t bh[4];
                ldsm4(bh, bBase + (uint32_t)(wc * 64 + np * 16) * SB + b_lane_off);
#pragma unroll
                for (int mi = 0; mi < 2; ++mi) {
#pragma unroll
                    for (int t = 0; t < 2; ++t)
                        mma_bf16(acc[mi][np * 2 + t], ah[mi], bh + 2 * t);
                }
            }
        }
        if (ch < 3) {
            CVT_A(nxt, false);      // writes other stage; overlaps in-flight cp.async
            CP_WAIT0();
        }
        __syncthreads();            // readers of cur done + writers of nxt visible
    }

    // ---- epilogue: logits (fast log), per-row top-2, argmax ----
    const int g = lane >> 2;
    const int tig = lane & 3;
#pragma unroll
    for (int mi = 0; mi < 2; ++mi) {
#pragma unroll
        for (int half = 0; half < 2; ++half) {
            int row = wr * 32 + mi * 16 + g + 8 * half;
            int grow = row0 + row;
            float x2r = x2s[row];
            const float* urow = u + (size_t)(grow < N ? grow : 0) * K_DIM + wc * 64;
            float best = -INFINITY, second = -INFINITY;
            int bidx = 0;
#pragma unroll
            for (int ni = 0; ni < 8; ++ni) {
                int col = ni * 8 + tig * 2;
                float2 uu = *reinterpret_cast<const float2*>(urow + col);
#pragma unroll
                for (int j = 0; j < 2; ++j) {
                    int k = wc * 64 + col + j;
                    float dot = acc[mi][ni][2 * half + j];
                    float sq = fmaxf(x2r - 2.f * dot + c2s[k], 0.f);
                    float uv = j ? uu.y : uu.x;
                    float gb = -__logf(-__logf(uv + 1e-10f) + 1e-10f);
                    float lg = sqrtf(sq) + gb;
                    if (lg > best) { second = best; best = lg; bidx = k; }
                    else if (lg > second) { second = lg; }
                }
            }
#pragma unroll
            for (int o = 1; o <= 2; o <<= 1) {
                float b2 = __shfl_xor_sync(0xffffffffu, best, o);
                float s2 = __shfl_xor_sync(0xffffffffu, second, o);
                int i2 = __shfl_xor_sync(0xffffffffu, bidx, o);
                float lo = fminf(best, b2);
                if (b2 > best || (b2 == best && i2 < bidx)) {
                    second = fmaxf(lo, s2); best = b2; bidx = i2;
                } else {
                    second = fmaxf(lo, second);
                }
            }
            if (tig == 0) {
                bvs[wc * 128 + row] = best;
                bss[wc * 128 + row] = second;
                bis[wc * 128 + row] = bidx;
            }
        }
    }
    __syncthreads();

    // combine halves; flag near-ties for exact fp32 recompute
    if (tid < 128) {
        float v0 = bvs[tid], v1 = bvs[128 + tid];
        float s0 = bss[tid], s1 = bss[128 + tid];
        bool h1 = (v1 > v0);
        float ball = h1 ? v1 : v0;
        float sall = fmaxf(fminf(v0, v1), h1 ? s1 : s0);
        idxs[tid] = h1 ? bis[128 + tid] : bis[tid];
        if (row0 + tid < N && ball - sall < 4e-3f) {
            int p = atomicAdd(fcnt, 1);
            flist[p] = tid;
        }
    }
    __syncthreads();

    // ---- exact fp32 fallback for flagged rows (~0.5/CTA) ----
    int nf = *fcnt;
    for (int f = 0; f < nf; ++f) {
        int row = flist[f];
        int grow = row0 + row;
        {
            int k = tid & 127, h = tid >> 7;
            const float* xr = seq + (size_t)grow * D_DIM + h * 128;
            const float* cr = C + (size_t)k * D_DIM + h * 128;
            float p = 0.f;
#pragma unroll 8
            for (int d = 0; d < 128; ++d) p = fmaf(xr[d], cr[d], p);
            bvs[tid] = p;
        }
        __syncthreads();
        if (tid < 128) {
            float dot = bvs[tid] + bvs[tid + 128];
            float sq = fmaxf(x2s[row] - 2.f * dot + c2s[tid], 0.f);
            float uv = u[(size_t)grow * K_DIM + tid];
            bss[tid] = sqrtf(sq) - logf(-logf(uv + 1e-10f) + 1e-10f);
        }
        __syncthreads();
        if (tid == 0) {
            float bv = -INFINITY; int bi = 0;
            for (int k = 0; k < K_DIM; ++k)
                if (bss[k] > bv) { bv = bss[k]; bi = k; }
            idxs[row] = bi;
        }
        __syncthreads();
    }

    // ---- coalesced one-hot store ----
#pragma unroll
    for (int it = 0; it < 16; ++it) {
        int item = tid + NTHREADS * it;
        int row = item >> 5;
        int c4 = item & 31;
        int grow = row0 + row;
        if (grow < N) {
            int hot = idxs[row];
            float4 o = make_float4(0.f, 0.f, 0.f, 0.f);
            if ((hot >> 2) == c4) reinterpret_cast<float*>(&o)[hot & 3] = 1.0f;
            *reinterpret_cast<float4*>(assign + (size_t)grow * K_DIM + 4 * c4) = o;
        }
    }
}

extern "C" void kernel_launch(void* const* d_in, const int* in_sizes, int n_in,
                              void* d_out, int out_size) {
    const float* seq = (const float*)d_in[0];  // [N,256]
    const float* u   = (const float*)d_in[1];  // [N,128]
    const float* C   = (const float*)d_in[2];  // [128,256]

    const int N = in_sizes[1] / K_DIM;
    float* out = (float*)d_out;
    float* assign = out;

    long long need_both = (long long)N * K_DIM + (long long)K_DIM * D_DIM;
    if ((long long)out_size >= need_both) {
        cudaMemcpyAsync(out, C, (size_t)K_DIM * D_DIM * sizeof(float),
                        cudaMemcpyDeviceToDevice);
        assign = out + K_DIM * D_DIM;
    }

    prep_kernel<<<1, NTHREADS>>>(C);

    cudaFuncSetAttribute(assign_kernel,
                         cudaFuncAttributeMaxDynamicSharedMemorySize, SMEM_TOTAL);
    int grid = (N + TILE_M - 1) / TILE_M;
    assign_kernel<<<grid, NTHREADS, SMEM_TOTAL>>>(seq, u, C, assign, N);
}

// round 8
// speedup vs baseline: 1.8150x; 1.0920x over previous
#include <cuda_runtime.h>
#include <cuda_bf16.h>
#include <cstdint>
#include <math.h>

#define K_DIM 128
#define D_DIM 256
#define TILE_M 128
#define NTHREADS 512
#define DC 64
#define SB 144               // smem row stride bytes (72 bf16): conflict-free ldmatrix
#define ATILE 18432          // 128 * 144
#define STAGE 36864          // A tile + B tile per stage
#define LW 132               // logits smem row stride (f32)

// ---- dynamic smem layout (bytes): two stages, logits aliased over stages ----
#define SMEM_A(s)   ((s) * STAGE)
#define SMEM_B(s)   ((s) * STAGE + ATILE)
#define SMEM_LOGITS 0                    // [128][132] f32 = 67584 B (aliases stages)
#define SMEM_MISC   73728
#define SMEM_C2     (SMEM_MISC + 0)      // 128 f32
#define SMEM_X2     (SMEM_MISC + 512)    // 128 f32
#define SMEM_IDX    (SMEM_MISC + 1024)   // 128 i32
#define SMEM_FCNT   (SMEM_MISC + 1536)
#define SMEM_FLIST  (SMEM_MISC + 1540)   // 128 i32
#define SMEM_SC1    (SMEM_MISC + 2052)   // 256 f32 fallback partials
#define SMEM_SC2    (SMEM_MISC + 3076)   // 128 f32 fallback logits
#define SMEM_TOTAL  (SMEM_MISC + 3600)   // 77328 B -> 2 CTAs/SM

__device__ float g_c2[K_DIM];
// Pre-converted B (bf16), per chunk, padded layout == smem image
__device__ __align__(16) unsigned char g_B[4 * ATILE];

// ---------------- PTX helpers ----------------
__device__ __forceinline__ uint32_t smem_u32(const void* p) {
    uint32_t a;
    asm("{ .reg .u64 t; cvta.to.shared.u64 t, %1; cvt.u32.u64 %0, t; }"
        : "=r"(a) : "l"(p));
    return a;
}
__device__ __forceinline__ void ldsm4(uint32_t* r, uint32_t addr) {
    asm volatile("ldmatrix.sync.aligned.m8n8.x4.shared.b16 {%0,%1,%2,%3}, [%4];"
                 : "=r"(r[0]), "=r"(r[1]), "=r"(r[2]), "=r"(r[3]) : "r"(addr));
}
__device__ __forceinline__ void mma_bf16(float* d, const uint32_t* a, const uint32_t* b) {
    asm volatile("mma.sync.aligned.m16n8k16.row.col.f32.bf16.bf16.f32 "
                 "{%0,%1,%2,%3}, {%4,%5,%6,%7}, {%8,%9}, {%0,%1,%2,%3};"
                 : "+f"(d[0]), "+f"(d[1]), "+f"(d[2]), "+f"(d[3])
                 : "r"(a[0]), "r"(a[1]), "r"(a[2]), "r"(a[3]), "r"(b[0]), "r"(b[1]));
}
__device__ __forceinline__ void cp16(uint32_t smaddr, const void* gaddr) {
    asm volatile("cp.async.ca.shared.global [%0], [%1], 16;"
                 :: "r"(smaddr), "l"(gaddr) : "memory");
}
#define CP_COMMIT() asm volatile("cp.async.commit_group;" ::: "memory")
#define CP_WAIT0()  asm volatile("cp.async.wait_group 0;" ::: "memory")

__device__ __forceinline__ uint32_t pack_bf2(float a, float b) {
    __nv_bfloat16 ha = __float2bfloat16_rn(a), hb = __float2bfloat16_rn(b);
    uint16_t ra = *reinterpret_cast<uint16_t*>(&ha);
    uint16_t rb = *reinterpret_cast<uint16_t*>(&hb);
    return (uint32_t)ra | ((uint32_t)rb << 16);
}

// ---------------- prep: ||c_k||^2 + pre-convert B bf16 in padded smem image ----------------
__global__ void prep_kernel(const float* __restrict__ C) {
    int tid = threadIdx.x;
    if (tid < K_DIM) {
        float s = 0.f;
        const float* row = C + (size_t)tid * D_DIM;
#pragma unroll 8
        for (int d = 0; d < D_DIM; ++d) s = fmaf(row[d], row[d], s);
        g_c2[tid] = s;
    }
    for (int i = tid; i < 4 * 128 * 64; i += 256) {
        int ch = i >> 13, r = (i >> 6) & 127, d = i & 63;
        float v = C[(size_t)r * D_DIM + ch * DC + d];
        __nv_bfloat16 h = __float2bfloat16_rn(v);
        *reinterpret_cast<uint16_t*>(&g_B[ch * ATILE + r * SB + d * 2]) =
            *reinterpret_cast<uint16_t*>(&h);
    }
}

// ---------------- main ----------------
__global__ __launch_bounds__(NTHREADS, 2)
void assign_kernel(const float* __restrict__ seq, const float* __restrict__ u,
                   const float* __restrict__ C, float* __restrict__ assign,
                   int N) {
    extern __shared__ char smem[];
    const uint32_t sm = smem_u32(smem);
    const int tid = threadIdx.x;
    const int wid = tid >> 5;
    const int lane = tid & 31;
    const int row0 = blockIdx.x * TILE_M;

    float* c2s = (float*)(smem + SMEM_C2);
    float* x2s = (float*)(smem + SMEM_X2);
    float* lgt = (float*)(smem + SMEM_LOGITS);
    int*   idxs = (int*)(smem + SMEM_IDX);
    int*   fcnt = (int*)(smem + SMEM_FCNT);
    int*   flist = (int*)(smem + SMEM_FLIST);
    float* sc1 = (float*)(smem + SMEM_SC1);
    float* sc2 = (float*)(smem + SMEM_SC2);

    if (tid < K_DIM) c2s[tid] = g_c2[tid];
    if (tid == 0) *fcnt = 0;

    const int wr = wid >> 1;       // 0..7: rows wr*16..+15
    const int wc = wid & 1;        // 0..1: cols wc*64..+63

    float acc[8][4];
#pragma unroll
    for (int ni = 0; ni < 8; ni++)
#pragma unroll
        for (int j = 0; j < 4; j++) acc[ni][j] = 0.f;

    float4 av[4];

#define LD_A(CH) do {                                                            \
    _Pragma("unroll")                                                            \
    for (int i = 0; i < 4; ++i) {                                                \
        int f = tid + NTHREADS * i;                                              \
        int row = f >> 4, c4 = f & 15, grow = row0 + row;                        \
        av[i] = make_float4(0.f, 0.f, 0.f, 0.f);                                 \
        if (grow < N)                                                            \
            av[i] = *reinterpret_cast<const float4*>(                            \
                seq + (size_t)grow * D_DIM + (CH) * DC + 4 * c4);                \
    }                                                                            \
} while (0)

#define CP_B(CH, S) do {                                                         \
    const unsigned char* src = g_B + (CH) * ATILE;                               \
    uint32_t dst = sm + SMEM_B(S);                                               \
    _Pragma("unroll")                                                            \
    for (int j = 0; j < 3; ++j) {                                                \
        int off = (tid + NTHREADS * j) * 16;                                     \
        if (off < ATILE) cp16(dst + off, src + off);                             \
    }                                                                            \
} while (0)

#define CVT_A(S, FIRST) do {                                                     \
    char* dst = smem + SMEM_A(S);                                                \
    _Pragma("unroll")                                                            \
    for (int i = 0; i < 4; ++i) {                                                \
        int f = tid + NTHREADS * i;                                              \
        int row = f >> 4, c4 = f & 15;                                           \
        float4 v = av[i];                                                        \
        float part = v.x * v.x + v.y * v.y + v.z * v.z + v.w * v.w;              \
        _Pragma("unroll")                                                        \
        for (int o = 8; o >= 1; o >>= 1)                                         \
            part += __shfl_xor_sync(0xffffffffu, part, o);                       \
        if ((lane & 15) == 0) {                                                  \
            if (FIRST) x2s[row] = part; else x2s[row] += part;                   \
        }                                                                        \
        *reinterpret_cast<uint2*>(dst + (uint32_t)row * SB + c4 * 8) =           \
            make_uint2(pack_bf2(v.x, v.y), pack_bf2(v.z, v.w));                  \
    }                                                                            \
} while (0)

    // ---- prologue: stage 0 holds chunk 0 ----
    CP_B(0, 0);
    CP_COMMIT();
    LD_A(0);
    CVT_A(0, true);
    CP_WAIT0();
    __syncthreads();

    // ---- pipelined mainloop: one sync per chunk ----
#pragma unroll
    for (int ch = 0; ch < 4; ++ch) {
        const int cur = ch & 1, nxt = cur ^ 1;
        if (ch < 3) {
            CP_B(ch + 1, nxt);      // other stage: overlaps MMA(cur), no hazard
            CP_COMMIT();
        }
        const uint32_t aBase = sm + SMEM_A(cur);
        const uint32_t bBase = sm + SMEM_B(cur);
#pragma unroll
        for (int ks = 0; ks < 4; ++ks) {
            uint32_t ah[4];
            ldsm4(ah, aBase + (uint32_t)(wr * 16 + (lane & 15)) * SB
                        + (uint32_t)(lane >> 4) * 16 + (uint32_t)ks * 32);
            const uint32_t b_lane_off =
                (uint32_t)((lane & 7) + ((lane >> 4) << 3)) * SB +
                (uint32_t)ks * 32 + (uint32_t)(((lane >> 3) & 1) << 4);
#pragma unroll
            for (int np = 0; np < 4; ++np) {
                uint32_t bh[4];
                ldsm4(bh, bBase + (uint32_t)(wc * 64 + np * 16) * SB + b_lane_off);
                mma_bf16(acc[np * 2 + 0], ah, bh + 0);
                mma_bf16(acc[np * 2 + 1], ah, bh + 2);
            }
        }
        if (ch < 3) {
            LD_A(ch + 1);           // MLP-4 burst; latency covered by other warps' MMA
            CVT_A(nxt, false);
            CP_WAIT0();
        }
        __syncthreads();
    }

    // ---- epilogue v2: dump dots to smem, then coalesced per-row pass ----
    {
        const int g = lane >> 2;       // 0..7
        const int tig = lane & 3;      // 0..3
#pragma unroll
        for (int half = 0; half < 2; ++half) {
            int row = wr * 16 + g + 8 * half;
#pragma unroll
            for (int ni = 0; ni < 8; ++ni) {
                int col = wc * 64 + ni * 8 + tig * 2;
                *reinterpret_cast<float2*>(&lgt[row * LW + col]) =
                    make_float2(acc[ni][2 * half], acc[ni][2 * half + 1]);
            }
        }
    }
    __syncthreads();

    // one warp per row (8 rows/warp); lanes span 128 cols, 4 each -> coalesced
    for (int r = 0; r < 8; ++r) {
        int row = wid * 8 + r;
        int grow = row0 + row;
        float x2r = x2s[row];
        float4 dots = *reinterpret_cast<const float4*>(&lgt[row * LW + lane * 4]);
        float4 c2v  = *reinterpret_cast<const float4*>(&c2s[lane * 4]);
        float4 uv   = *reinterpret_cast<const float4*>(
            u + (size_t)(grow < N ? grow : 0) * K_DIM + lane * 4);
        float best = -INFINITY, second = -INFINITY;
        int bidx = 0;
#pragma unroll
        for (int q = 0; q < 4; ++q) {
            float dot = (&dots.x)[q];
            float sq = fmaxf(x2r - 2.f * dot + (&c2v.x)[q], 0.f);
            float us = (&uv.x)[q];
            float gb = -__logf(-__logf(us + 1e-10f) + 1e-10f);
            float lg = sqrtf(sq) + gb;
            if (lg > best) { second = best; best = lg; bidx = lane * 4 + q; }
            else if (lg > second) { second = lg; }
        }
#pragma unroll
        for (int o = 1; o <= 16; o <<= 1) {
            float b2 = __shfl_xor_sync(0xffffffffu, best, o);
            float s2 = __shfl_xor_sync(0xffffffffu, second, o);
            int i2 = __shfl_xor_sync(0xffffffffu, bidx, o);
            float lo = fminf(best, b2);
            if (b2 > best || (b2 == best && i2 < bidx)) {
                second = fmaxf(lo, s2); best = b2; bidx = i2;
            } else {
                second = fmaxf(lo, second);
            }
        }
        if (lane == 0) {
            idxs[row] = bidx;
            if (grow < N && best - second < 4e-3f) {
                int p = atomicAdd(fcnt, 1);
                flist[p] = row;
            }
        }
    }
    __syncthreads();

    // ---- exact fp32 fallback for flagged rows (~0.5/CTA) ----
    int nf = *fcnt;
    for (int f = 0; f < nf; ++f) {
        int row = flist[f];
        int grow = row0 + row;
        if (tid < 256) {
            int k = tid & 127, h = tid >> 7;
            const float* xr = seq + (size_t)grow * D_DIM + h * 128;
            const float* cr = C + (size_t)k * D_DIM + h * 128;
            float p = 0.f;
#pragma unroll 8
            for (int d = 0; d < 128; ++d) p = fmaf(xr[d], cr[d], p);
            sc1[tid] = p;
        }
        __syncthreads();
        if (tid < 128) {
            float dot = sc1[tid] + sc1[tid + 128];
            float sq = fmaxf(x2s[row] - 2.f * dot + c2s[tid], 0.f);
            float us = u[(size_t)grow * K_DIM + tid];
            sc2[tid] = sqrtf(sq) - logf(-logf(us + 1e-10f) + 1e-10f);
        }
        __syncthreads();
        if (tid == 0) {
            float bv = -INFINITY; int bi = 0;
            for (int k = 0; k < K_DIM; ++k)
                if (sc2[k] > bv) { bv = sc2[k]; bi = k; }
            idxs[row] = bi;
        }
        __syncthreads();
    }

    // ---- coalesced one-hot store ----
#pragma unroll
    for (int it = 0; it < 8; ++it) {
        int item = tid + NTHREADS * it;   // 0..4095
        int row = item >> 5;
        int c4 = item & 31;
        int grow = row0 + row;
        if (grow < N) {
            int hot = idxs[row];
            float4 o = make_float4(0.f, 0.f, 0.f, 0.f);
            if ((hot >> 2) == c4) reinterpret_cast<float*>(&o)[hot & 3] = 1.0f;
            *reinterpret_cast<float4*>(assign + (size_t)grow * K_DIM + 4 * c4) = o;
        }
    }
}

extern "C" void kernel_launch(void* const* d_in, const int* in_sizes, int n_in,
                              void* d_out, int out_size) {
    const float* seq = (const float*)d_in[0];  // [N,256]
    const float* u   = (const float*)d_in[1];  // [N,128]
    const float* C   = (const float*)d_in[2];  // [128,256]

    const int N = in_sizes[1] / K_DIM;
    float* out = (float*)d_out;
    float* assign = out;

    long long need_both = (long long)N * K_DIM + (long long)K_DIM * D_DIM;
    if ((long long)out_size >= need_both) {
        cudaMemcpyAsync(out, C, (size_t)K_DIM * D_DIM * sizeof(float),
                        cudaMemcpyDeviceToDevice);
        assign = out + K_DIM * D_DIM;
    }

    prep_kernel<<<1, 256>>>(C);

    cudaFuncSetAttribute(assign_kernel,
                         cudaFuncAttributeMaxDynamicSharedMemorySize, SMEM_TOTAL);
    int grid = (N + TILE_M - 1) / TILE_M;
    assign_kernel<<<grid, NTHREADS, SMEM_TOTAL>>>(seq, u, C, assign, N);
}